// round 13
// baseline (speedup 1.0000x reference)
#include <cuda_runtime.h>
#include <cstdint>

#define BLOCK 256

// ---------------------------------------------------------------------------
// BinaryTreeRNN: out[i] = tree_combine( x[i,0:16] @ W_leaf^T + b_leaf )
// 2-node graph:
//   (1) setup kernel folds ALL params (W pair-interleave, softmax+w -> node
//       coeffs, bias pairs) and writes them DIRECTLY into the __constant__
//       bank via its global-space address (no memcpy node, no staging).
//   (2) main kernel == R9/R3 body: every per-row parameter access rides the
//       constant port (LDC/LDCU), zero param L1TEX traffic, bias folded
//       into the packed fp32x2 accumulator init.
// ---------------------------------------------------------------------------

struct __align__(16) CParams {
    float2 Wp[4][16];   // [pair p][k] = (W[2p][k], W[2p+1][k])
    float2 bp[4];       // (b_leaf[2p], b_leaf[2p+1])
    float4 node[7];     // (A, M, C, b): val = A*s + M*l*r + C*sin(s) + b
};

__constant__ CParams cP;

__global__ void setup_kernel(CParams* __restrict__ dst,
                             const float* __restrict__ W,
                             const float* __restrict__ bl,
                             const float* __restrict__ w0,
                             const float* __restrict__ w1,
                             const float* __restrict__ w2,
                             const float* __restrict__ b0,
                             const float* __restrict__ b1,
                             const float* __restrict__ b2,
                             const float* __restrict__ om0,
                             const float* __restrict__ om1,
                             const float* __restrict__ om2)
{
    int t = threadIdx.x;
    if (t < 64) {
        int p = t >> 4, k = t & 15;
        dst->Wp[p][k] = make_float2(W[(2 * p) * 16 + k], W[(2 * p + 1) * 16 + k]);
    } else if (t < 68) {
        int p = t - 64;
        dst->bp[p] = make_float2(bl[2 * p], bl[2 * p + 1]);
    } else if (t < 75) {
        int i = t - 68;   // 0-3: level2, 4-5: level1, 6: level0
        const float* om;
        float w, b;
        if (i < 4)      { om = om2 + 4 * i;       w = w2[i];     b = b2[i]; }
        else if (i < 6) { om = om1 + 4 * (i - 4); w = w1[i - 4]; b = b1[i - 4]; }
        else            { om = om0;               w = w0[0];     b = b0[0]; }
        float e0 = __expf(om[0]);
        float e1 = __expf(om[1]);
        float e2 = __expf(om[2]);
        float e3 = __expf(om[3]);
        float inv = __fdividef(w, e0 + e1 + e2 + e3);  // fold w into coeffs
        dst->node[i] = make_float4((e0 + e3) * inv, e1 * inv, e2 * inv, b);
    }
    __threadfence();   // push stores to L2 (coherence point for LDC fills)
}

// ---- packed fp32x2 helpers (sm_103a) --------------------------------------

__device__ __forceinline__ unsigned long long fma2(unsigned long long a,
                                                   unsigned long long b,
                                                   unsigned long long c)
{
    unsigned long long d;
    asm("fma.rn.f32x2 %0, %1, %2, %3;" : "=l"(d) : "l"(a), "l"(b), "l"(c));
    return d;
}

__device__ __forceinline__ unsigned long long dup2(float v)
{
    unsigned long long d;
    asm("mov.b64 %0, {%1, %1};" : "=l"(d) : "f"(v));
    return d;
}

__device__ __forceinline__ void unpack2(unsigned long long v, float& lo, float& hi)
{
    asm("mov.b64 {%0, %1}, %2;" : "=f"(lo), "=f"(hi) : "l"(v));
}

// ---- main kernel (R9/R3 body) -----------------------------------------------

__global__ void __launch_bounds__(BLOCK)
tree_rnn_kernel(const float4* __restrict__ x4, float* __restrict__ out, int n)
{
    __shared__ float4 tile[BLOCK * 4];   // 256 rows x 16 floats, XOR-swizzled
    const int t = threadIdx.x;

    // coalesced tile load, XOR-swizzled store (conflict-free both phases)
    const int n4 = n * 4;
    const int base4 = blockIdx.x * (BLOCK * 4);
#pragma unroll
    for (int j = 0; j < 4; j++) {
        int li = j * BLOCK + t;
        int g4 = base4 + li;
        float4 v;
        if (g4 < n4) v = x4[g4];
        else         v = make_float4(0.f, 0.f, 0.f, 0.f);
        int r = li >> 2;
        int q = li & 3;
        tile[(r << 2) + (q ^ ((r >> 1) & 3))] = v;
    }
    __syncthreads();

    const int row = blockIdx.x * BLOCK + t;
    if (row >= n) return;

    // gather own row (conflict-free via matching swizzle)
    const int swz = (t >> 1) & 3;
    float4 v0 = tile[(t << 2) + (0 ^ swz)];
    float4 v1 = tile[(t << 2) + (1 ^ swz)];
    float4 v2 = tile[(t << 2) + (2 ^ swz)];
    float4 v3 = tile[(t << 2) + (3 ^ swz)];

    unsigned long long xb[16];
    xb[0]  = dup2(v0.x); xb[1]  = dup2(v0.y); xb[2]  = dup2(v0.z); xb[3]  = dup2(v0.w);
    xb[4]  = dup2(v1.x); xb[5]  = dup2(v1.y); xb[6]  = dup2(v1.z); xb[7]  = dup2(v1.w);
    xb[8]  = dup2(v2.x); xb[9]  = dup2(v2.y); xb[10] = dup2(v2.z); xb[11] = dup2(v2.w);
    xb[12] = dup2(v3.x); xb[13] = dup2(v3.y); xb[14] = dup2(v3.z); xb[15] = dup2(v3.w);

    // leaf matvec: weights from the constant port (no L1TEX traffic),
    // bias pre-loaded into the packed accumulator
    float h[8];
#pragma unroll
    for (int p = 0; p < 4; p++) {
        unsigned long long acc =
            *reinterpret_cast<const unsigned long long*>(&cP.bp[p]);
#pragma unroll
        for (int k2 = 0; k2 < 8; k2++) {
            ulonglong2 w = *reinterpret_cast<const ulonglong2*>(&cP.Wp[p][2 * k2]);
            acc = fma2(w.x, xb[2 * k2 + 0], acc);
            acc = fma2(w.y, xb[2 * k2 + 1], acc);
        }
        unpack2(acc, h[2 * p + 0], h[2 * p + 1]);
    }

    // tree combine: val = A*s + M*(l*r) + C*sin(s) + b
    float g[4];
#pragma unroll
    for (int k = 0; k < 4; k++) {
        float4 np = cP.node[k];
        float l = h[2 * k], r = h[2 * k + 1];
        float s = l + r;
        g[k] = fmaf(np.x, s, fmaf(np.y, l * r, fmaf(np.z, __sinf(s), np.w)));
    }
    float u[2];
#pragma unroll
    for (int k = 0; k < 2; k++) {
        float4 np = cP.node[4 + k];
        float l = g[2 * k], r = g[2 * k + 1];
        float s = l + r;
        u[k] = fmaf(np.x, s, fmaf(np.y, l * r, fmaf(np.z, __sinf(s), np.w)));
    }
    {
        float4 np = cP.node[6];
        float l = u[0], r = u[1];
        float s = l + r;
        out[row] = fmaf(np.x, s, fmaf(np.y, l * r, fmaf(np.z, __sinf(s), np.w)));
    }
}

extern "C" void kernel_launch(void* const* d_in, const int* in_sizes, int n_in,
                              void* d_out, int out_size)
{
    const float* x      = (const float*)d_in[0];
    const float* W_leaf = (const float*)d_in[1];
    const float* b_leaf = (const float*)d_in[2];
    const float* w0     = (const float*)d_in[3];
    const float* w1     = (const float*)d_in[4];
    const float* w2     = (const float*)d_in[5];
    const float* b0     = (const float*)d_in[6];
    const float* b1     = (const float*)d_in[7];
    const float* b2     = (const float*)d_in[8];
    const float* om0    = (const float*)d_in[9];
    const float* om1    = (const float*)d_in[10];
    const float* om2    = (const float*)d_in[11];

    int n = in_sizes[0] / 16;

    // node 1: fold params and write DIRECTLY into the constant bank
    void* cp_ptr = nullptr;
    cudaGetSymbolAddress(&cp_ptr, cP);
    setup_kernel<<<1, 128>>>((CParams*)cp_ptr, W_leaf, b_leaf,
                             w0, w1, w2, b0, b1, b2, om0, om1, om2);

    // node 2: main kernel (reads cP via the constant port)
    int blocks = (n + BLOCK - 1) / BLOCK;
    tree_rnn_kernel<<<blocks, BLOCK>>>(
        reinterpret_cast<const float4*>(x), (float*)d_out, n);
}

// round 14
// speedup vs baseline: 1.0088x; 1.0088x over previous
#include <cuda_runtime.h>
#include <cstdint>

#define BLOCK 256

// ---------------------------------------------------------------------------
// BinaryTreeRNN: out[i] = tree_combine( x[i,0:16] @ W_leaf^T + b_leaf )
// 2-node graph with PDL overlap:
//   (1) setup kernel folds ALL params and writes them DIRECTLY into the
//       __constant__ bank (device-write coherence verified in R13), then
//       triggers dependent launch early.
//   (2) main kernel launched with ProgrammaticStreamSerialization: it starts
//       while setup runs, issues its x-tile LDG/STS phase (independent of
//       params), and only then griddepcontrol.wait's before the first
//       constant-port read. The kernel->kernel gap (~3us measured) hides
//       under the tile loads.
// ---------------------------------------------------------------------------

struct __align__(16) CParams {
    float2 Wp[4][16];   // [pair p][k] = (W[2p][k], W[2p+1][k])
    float2 bp[4];       // (b_leaf[2p], b_leaf[2p+1])
    float4 node[7];     // (A, M, C, b): val = A*s + M*l*r + C*sin(s) + b
};

__constant__ CParams cP;

__global__ void setup_kernel(CParams* __restrict__ dst,
                             const float* __restrict__ W,
                             const float* __restrict__ bl,
                             const float* __restrict__ w0,
                             const float* __restrict__ w1,
                             const float* __restrict__ w2,
                             const float* __restrict__ b0,
                             const float* __restrict__ b1,
                             const float* __restrict__ b2,
                             const float* __restrict__ om0,
                             const float* __restrict__ om1,
                             const float* __restrict__ om2)
{
    int t = threadIdx.x;
    if (t < 64) {
        int p = t >> 4, k = t & 15;
        dst->Wp[p][k] = make_float2(W[(2 * p) * 16 + k], W[(2 * p + 1) * 16 + k]);
    } else if (t < 68) {
        int p = t - 64;
        dst->bp[p] = make_float2(bl[2 * p], bl[2 * p + 1]);
    } else if (t < 75) {
        int i = t - 68;   // 0-3: level2, 4-5: level1, 6: level0
        const float* om;
        float w, b;
        if (i < 4)      { om = om2 + 4 * i;       w = w2[i];     b = b2[i]; }
        else if (i < 6) { om = om1 + 4 * (i - 4); w = w1[i - 4]; b = b1[i - 4]; }
        else            { om = om0;               w = w0[0];     b = b0[0]; }
        float e0 = __expf(om[0]);
        float e1 = __expf(om[1]);
        float e2 = __expf(om[2]);
        float e3 = __expf(om[3]);
        float inv = __fdividef(w, e0 + e1 + e2 + e3);  // fold w into coeffs
        dst->node[i] = make_float4((e0 + e3) * inv, e1 * inv, e2 * inv, b);
    }
    __threadfence();   // push stores to L2 (coherence point for LDC fills)
    __syncthreads();
    // signal dependents (PDL): our writes are flushed; let main proceed
    asm volatile("griddepcontrol.launch_dependents;" ::: "memory");
}

// ---- packed fp32x2 helpers (sm_103a) --------------------------------------

__device__ __forceinline__ unsigned long long fma2(unsigned long long a,
                                                   unsigned long long b,
                                                   unsigned long long c)
{
    unsigned long long d;
    asm("fma.rn.f32x2 %0, %1, %2, %3;" : "=l"(d) : "l"(a), "l"(b), "l"(c));
    return d;
}

__device__ __forceinline__ unsigned long long dup2(float v)
{
    unsigned long long d;
    asm("mov.b64 %0, {%1, %1};" : "=l"(d) : "f"(v));
    return d;
}

__device__ __forceinline__ void unpack2(unsigned long long v, float& lo, float& hi)
{
    asm("mov.b64 {%0, %1}, %2;" : "=f"(lo), "=f"(hi) : "l"(v));
}

// ---- main kernel (R9/R3 body + PDL wait) ------------------------------------

__global__ void __launch_bounds__(BLOCK)
tree_rnn_kernel(const float4* __restrict__ x4, float* __restrict__ out, int n)
{
    __shared__ float4 tile[BLOCK * 4];   // 256 rows x 16 floats, XOR-swizzled
    const int t = threadIdx.x;

    // coalesced tile load, XOR-swizzled store — independent of cP, so it
    // runs while the setup kernel is still in flight (PDL overlap)
    const int n4 = n * 4;
    const int base4 = blockIdx.x * (BLOCK * 4);
#pragma unroll
    for (int j = 0; j < 4; j++) {
        int li = j * BLOCK + t;
        int g4 = base4 + li;
        float4 v;
        if (g4 < n4) v = x4[g4];
        else         v = make_float4(0.f, 0.f, 0.f, 0.f);
        int r = li >> 2;
        int q = li & 3;
        tile[(r << 2) + (q ^ ((r >> 1) & 3))] = v;
    }

    // wait for the setup kernel's constant-bank writes before touching cP
    asm volatile("griddepcontrol.wait;" ::: "memory");
    __syncthreads();

    const int row = blockIdx.x * BLOCK + t;
    if (row >= n) return;

    // gather own row (conflict-free via matching swizzle)
    const int swz = (t >> 1) & 3;
    float4 v0 = tile[(t << 2) + (0 ^ swz)];
    float4 v1 = tile[(t << 2) + (1 ^ swz)];
    float4 v2 = tile[(t << 2) + (2 ^ swz)];
    float4 v3 = tile[(t << 2) + (3 ^ swz)];

    unsigned long long xb[16];
    xb[0]  = dup2(v0.x); xb[1]  = dup2(v0.y); xb[2]  = dup2(v0.z); xb[3]  = dup2(v0.w);
    xb[4]  = dup2(v1.x); xb[5]  = dup2(v1.y); xb[6]  = dup2(v1.z); xb[7]  = dup2(v1.w);
    xb[8]  = dup2(v2.x); xb[9]  = dup2(v2.y); xb[10] = dup2(v2.z); xb[11] = dup2(v2.w);
    xb[12] = dup2(v3.x); xb[13] = dup2(v3.y); xb[14] = dup2(v3.z); xb[15] = dup2(v3.w);

    // leaf matvec: weights from the constant port (no L1TEX traffic),
    // bias pre-loaded into the packed accumulator
    float h[8];
#pragma unroll
    for (int p = 0; p < 4; p++) {
        unsigned long long acc =
            *reinterpret_cast<const unsigned long long*>(&cP.bp[p]);
#pragma unroll
        for (int k2 = 0; k2 < 8; k2++) {
            ulonglong2 w = *reinterpret_cast<const ulonglong2*>(&cP.Wp[p][2 * k2]);
            acc = fma2(w.x, xb[2 * k2 + 0], acc);
            acc = fma2(w.y, xb[2 * k2 + 1], acc);
        }
        unpack2(acc, h[2 * p + 0], h[2 * p + 1]);
    }

    // tree combine: val = A*s + M*(l*r) + C*sin(s) + b
    float g[4];
#pragma unroll
    for (int k = 0; k < 4; k++) {
        float4 np = cP.node[k];
        float l = h[2 * k], r = h[2 * k + 1];
        float s = l + r;
        g[k] = fmaf(np.x, s, fmaf(np.y, l * r, fmaf(np.z, __sinf(s), np.w)));
    }
    float u[2];
#pragma unroll
    for (int k = 0; k < 2; k++) {
        float4 np = cP.node[4 + k];
        float l = g[2 * k], r = g[2 * k + 1];
        float s = l + r;
        u[k] = fmaf(np.x, s, fmaf(np.y, l * r, fmaf(np.z, __sinf(s), np.w)));
    }
    {
        float4 np = cP.node[6];
        float l = u[0], r = u[1];
        float s = l + r;
        out[row] = fmaf(np.x, s, fmaf(np.y, l * r, fmaf(np.z, __sinf(s), np.w)));
    }
}

extern "C" void kernel_launch(void* const* d_in, const int* in_sizes, int n_in,
                              void* d_out, int out_size)
{
    const float* x      = (const float*)d_in[0];
    const float* W_leaf = (const float*)d_in[1];
    const float* b_leaf = (const float*)d_in[2];
    const float* w0     = (const float*)d_in[3];
    const float* w1     = (const float*)d_in[4];
    const float* w2     = (const float*)d_in[5];
    const float* b0     = (const float*)d_in[6];
    const float* b1     = (const float*)d_in[7];
    const float* b2     = (const float*)d_in[8];
    const float* om0    = (const float*)d_in[9];
    const float* om1    = (const float*)d_in[10];
    const float* om2    = (const float*)d_in[11];

    int n = in_sizes[0] / 16;

    // node 1: fold params and write DIRECTLY into the constant bank
    void* cp_ptr = nullptr;
    cudaGetSymbolAddress(&cp_ptr, cP);
    setup_kernel<<<1, 128>>>((CParams*)cp_ptr, W_leaf, b_leaf,
                             w0, w1, w2, b0, b1, b2, om0, om1, om2);

    // node 2: main kernel with programmatic dependent launch (overlaps the
    // setup kernel + inter-kernel gap with its own LDG phase)
    int blocks = (n + BLOCK - 1) / BLOCK;

    cudaLaunchConfig_t cfg = {};
    cfg.gridDim  = dim3((unsigned)blocks, 1, 1);
    cfg.blockDim = dim3(BLOCK, 1, 1);
    cfg.dynamicSmemBytes = 0;
    cfg.stream = 0;
    cudaLaunchAttribute attrs[1];
    attrs[0].id = cudaLaunchAttributeProgrammaticStreamSerialization;
    attrs[0].val.programmaticStreamSerializationAllowed = 1;
    cfg.attrs = attrs;
    cfg.numAttrs = 1;

    const float4* x4 = reinterpret_cast<const float4*>(x);
    float* outp = (float*)d_out;
    cudaLaunchKernelEx(&cfg, tree_rnn_kernel, x4, outp, n);
}

// round 15
// speedup vs baseline: 1.0222x; 1.0133x over previous
#include <cuda_runtime.h>
#include <cstdint>

#define BLOCK 256

// ---------------------------------------------------------------------------
// BinaryTreeRNN: out[i] = tree_combine( x[i,0:16] @ W_leaf^T + b_leaf )
// 2-node graph with PDL overlap (R14 structure) + WARP-LOCAL tile slices:
//   (1) setup kernel folds ALL params and writes them DIRECTLY into the
//       __constant__ bank (device-write coherence verified in R13).
//   (2) main kernel: each warp owns a private 2 KB smem slice for its 32
//       rows -> only __syncwarp (no block barrier), so 64 independent
//       load/compute pipelines per SM keep DRAM fed instead of 8
//       phase-locked warpsets.
// ---------------------------------------------------------------------------

struct __align__(16) CParams {
    float2 Wp[4][16];   // [pair p][k] = (W[2p][k], W[2p+1][k])
    float2 bp[4];       // (b_leaf[2p], b_leaf[2p+1])
    float4 node[7];     // (A, M, C, b): val = A*s + M*l*r + C*sin(s) + b
};

__constant__ CParams cP;

__global__ void setup_kernel(CParams* __restrict__ dst,
                             const float* __restrict__ W,
                             const float* __restrict__ bl,
                             const float* __restrict__ w0,
                             const float* __restrict__ w1,
                             const float* __restrict__ w2,
                             const float* __restrict__ b0,
                             const float* __restrict__ b1,
                             const float* __restrict__ b2,
                             const float* __restrict__ om0,
                             const float* __restrict__ om1,
                             const float* __restrict__ om2)
{
    int t = threadIdx.x;
    if (t < 64) {
        int p = t >> 4, k = t & 15;
        dst->Wp[p][k] = make_float2(W[(2 * p) * 16 + k], W[(2 * p + 1) * 16 + k]);
    } else if (t < 68) {
        int p = t - 64;
        dst->bp[p] = make_float2(bl[2 * p], bl[2 * p + 1]);
    } else if (t < 75) {
        int i = t - 68;   // 0-3: level2, 4-5: level1, 6: level0
        const float* om;
        float w, b;
        if (i < 4)      { om = om2 + 4 * i;       w = w2[i];     b = b2[i]; }
        else if (i < 6) { om = om1 + 4 * (i - 4); w = w1[i - 4]; b = b1[i - 4]; }
        else            { om = om0;               w = w0[0];     b = b0[0]; }
        float e0 = __expf(om[0]);
        float e1 = __expf(om[1]);
        float e2 = __expf(om[2]);
        float e3 = __expf(om[3]);
        float inv = __fdividef(w, e0 + e1 + e2 + e3);  // fold w into coeffs
        dst->node[i] = make_float4((e0 + e3) * inv, e1 * inv, e2 * inv, b);
    }
    __threadfence();   // push stores to L2 (coherence point for LDC fills)
    __syncthreads();
    asm volatile("griddepcontrol.launch_dependents;" ::: "memory");
}

// ---- packed fp32x2 helpers (sm_103a) --------------------------------------

__device__ __forceinline__ unsigned long long fma2(unsigned long long a,
                                                   unsigned long long b,
                                                   unsigned long long c)
{
    unsigned long long d;
    asm("fma.rn.f32x2 %0, %1, %2, %3;" : "=l"(d) : "l"(a), "l"(b), "l"(c));
    return d;
}

__device__ __forceinline__ unsigned long long dup2(float v)
{
    unsigned long long d;
    asm("mov.b64 %0, {%1, %1};" : "=l"(d) : "f"(v));
    return d;
}

__device__ __forceinline__ void unpack2(unsigned long long v, float& lo, float& hi)
{
    asm("mov.b64 {%0, %1}, %2;" : "=f"(lo), "=f"(hi) : "l"(v));
}

// ---- main kernel -----------------------------------------------------------

__global__ void __launch_bounds__(BLOCK)
tree_rnn_kernel(const float4* __restrict__ x4, float* __restrict__ out, int n)
{
    __shared__ float4 tile[8][128];   // per-warp 2KB slice: 32 rows x 4 f4
    const int t = threadIdx.x;
    const int lane = t & 31;
    const int w = t >> 5;
    float4* ts = tile[w];

    // warp-local coalesced load + XOR-swizzled store (conflict-free)
    const int n4 = n * 4;
    const int base4 = blockIdx.x * (BLOCK * 4) + w * 128;
#pragma unroll
    for (int m = 0; m < 4; m++) {
        int li = m * 32 + lane;           // 0..127 within this warp's tile
        int g4 = base4 + li;
        float4 v;
        if (g4 < n4) v = x4[g4];
        else         v = make_float4(0.f, 0.f, 0.f, 0.f);
        int r = li >> 2;
        int q = li & 3;
        ts[(r << 2) + (q ^ ((r >> 1) & 3))] = v;
    }

    // wait for setup kernel's constant-bank writes (PDL), then warp-sync
    asm volatile("griddepcontrol.wait;" ::: "memory");
    __syncwarp();

    const int row = blockIdx.x * BLOCK + w * 32 + lane;
    if (row >= n) return;

    // gather own row (conflict-free via matching swizzle)
    const int swz = (lane >> 1) & 3;
    float4 v0 = ts[(lane << 2) + (0 ^ swz)];
    float4 v1 = ts[(lane << 2) + (1 ^ swz)];
    float4 v2 = ts[(lane << 2) + (2 ^ swz)];
    float4 v3 = ts[(lane << 2) + (3 ^ swz)];

    unsigned long long xb[16];
    xb[0]  = dup2(v0.x); xb[1]  = dup2(v0.y); xb[2]  = dup2(v0.z); xb[3]  = dup2(v0.w);
    xb[4]  = dup2(v1.x); xb[5]  = dup2(v1.y); xb[6]  = dup2(v1.z); xb[7]  = dup2(v1.w);
    xb[8]  = dup2(v2.x); xb[9]  = dup2(v2.y); xb[10] = dup2(v2.z); xb[11] = dup2(v2.w);
    xb[12] = dup2(v3.x); xb[13] = dup2(v3.y); xb[14] = dup2(v3.z); xb[15] = dup2(v3.w);

    // leaf matvec: weights from the constant port (no L1TEX traffic),
    // bias pre-loaded into the packed accumulator
    float h[8];
#pragma unroll
    for (int p = 0; p < 4; p++) {
        unsigned long long acc =
            *reinterpret_cast<const unsigned long long*>(&cP.bp[p]);
#pragma unroll
        for (int k2 = 0; k2 < 8; k2++) {
            ulonglong2 wq = *reinterpret_cast<const ulonglong2*>(&cP.Wp[p][2 * k2]);
            acc = fma2(wq.x, xb[2 * k2 + 0], acc);
            acc = fma2(wq.y, xb[2 * k2 + 1], acc);
        }
        unpack2(acc, h[2 * p + 0], h[2 * p + 1]);
    }

    // tree combine: val = A*s + M*(l*r) + C*sin(s) + b
    float g[4];
#pragma unroll
    for (int k = 0; k < 4; k++) {
        float4 np = cP.node[k];
        float l = h[2 * k], r = h[2 * k + 1];
        float s = l + r;
        g[k] = fmaf(np.x, s, fmaf(np.y, l * r, fmaf(np.z, __sinf(s), np.w)));
    }
    float u[2];
#pragma unroll
    for (int k = 0; k < 2; k++) {
        float4 np = cP.node[4 + k];
        float l = g[2 * k], r = g[2 * k + 1];
        float s = l + r;
        u[k] = fmaf(np.x, s, fmaf(np.y, l * r, fmaf(np.z, __sinf(s), np.w)));
    }
    {
        float4 np = cP.node[6];
        float l = u[0], r = u[1];
        float s = l + r;
        out[row] = fmaf(np.x, s, fmaf(np.y, l * r, fmaf(np.z, __sinf(s), np.w)));
    }
}

extern "C" void kernel_launch(void* const* d_in, const int* in_sizes, int n_in,
                              void* d_out, int out_size)
{
    const float* x      = (const float*)d_in[0];
    const float* W_leaf = (const float*)d_in[1];
    const float* b_leaf = (const float*)d_in[2];
    const float* w0     = (const float*)d_in[3];
    const float* w1     = (const float*)d_in[4];
    const float* w2     = (const float*)d_in[5];
    const float* b0     = (const float*)d_in[6];
    const float* b1     = (const float*)d_in[7];
    const float* b2     = (const float*)d_in[8];
    const float* om0    = (const float*)d_in[9];
    const float* om1    = (const float*)d_in[10];
    const float* om2    = (const float*)d_in[11];

    int n = in_sizes[0] / 16;

    // node 1: fold params and write DIRECTLY into the constant bank
    void* cp_ptr = nullptr;
    cudaGetSymbolAddress(&cp_ptr, cP);
    setup_kernel<<<1, 128>>>((CParams*)cp_ptr, W_leaf, b_leaf,
                             w0, w1, w2, b0, b1, b2, om0, om1, om2);

    // node 2: main kernel with programmatic dependent launch
    int blocks = (n + BLOCK - 1) / BLOCK;

    cudaLaunchConfig_t cfg = {};
    cfg.gridDim  = dim3((unsigned)blocks, 1, 1);
    cfg.blockDim = dim3(BLOCK, 1, 1);
    cfg.dynamicSmemBytes = 0;
    cfg.stream = 0;
    cudaLaunchAttribute attrs[1];
    attrs[0].id = cudaLaunchAttributeProgrammaticStreamSerialization;
    attrs[0].val.programmaticStreamSerializationAllowed = 1;
    cfg.attrs = attrs;
    cfg.numAttrs = 1;

    const float4* x4 = reinterpret_cast<const float4*>(x);
    float* outp = (float*)d_out;
    cudaLaunchKernelEx(&cfg, tree_rnn_kernel, x4, outp, n);
}